// round 6
// baseline (speedup 1.0000x reference)
#include <cuda_runtime.h>

#define NMAX 50000
#define EMAX 1600000

// ---------------- static device scratch ----------------
__device__ int   g_cnt[NMAX];          // zero at load; re-zeroed by scan each run
__device__ int   g_off[NMAX + 1];
__device__ int   g_cur[NMAX];
__device__ int   g_epk[EMAX];          // src node per CSR slot
__device__ int   g_slot[EMAX];         // edge id -> CSR slot
__device__ float g_q[NMAX * 64];
__device__ float g_k[NMAX * 64];
__device__ float g_v[NMAX * 64];
__device__ float g_agg[NMAX * 64];
__device__ float g_h[NMAX * 64];
__device__ float g_A[NMAX * 32];
__device__ float g_B[NMAX * 32];
__device__ float g_e[EMAX * 32];
__device__ float g_bias[EMAX * 4];     // score bias in CSR-slot order

// ---------------- f32x2 packed helpers (sm_103a FFMA2 path) ----------------
__device__ __forceinline__ unsigned long long pk2(float a, float b) {
    unsigned long long r;
    asm("mov.b64 %0, {%1, %2};" : "=l"(r) : "f"(a), "f"(b));
    return r;
}
__device__ __forceinline__ void upk2(unsigned long long v, float& a, float& b) {
    asm("mov.b64 {%0, %1}, %2;" : "=f"(a), "=f"(b) : "l"(v));
}
__device__ __forceinline__ unsigned long long fma2(unsigned long long a,
                                                   unsigned long long b,
                                                   unsigned long long c) {
    unsigned long long d;
    asm("fma.rn.f32x2 %0, %1, %2, %3;" : "=l"(d) : "l"(a), "l"(b), "l"(c));
    return d;
}

// ---------------- count ----------------
__global__ void k_count(const int* __restrict__ dst, int e) {
    int i = blockIdx.x * blockDim.x + threadIdx.x;
    if (i < e) atomicAdd(&g_cnt[dst[i]], 1);
}

// ---------------- fused: block0 = exclusive scan (+re-zero cnt), rest = qkv proj ----------------
__global__ void k_scanproj(int n, const float* __restrict__ hin, int useG,
                           const float* __restrict__ Wq, const float* __restrict__ Wk,
                           const float* __restrict__ Wv, int withScan) {
    __shared__ float sq[4096], sk[4096], sv[4096];
    __shared__ int swi[32];
    int t = threadIdx.x;
    if (withScan && blockIdx.x == 0) {
        int lane = t & 31, w = t >> 5;
        int carry = 0;
        for (int base = 0; base < n; base += 1024) {
            int i = base + t;
            int v = (i < n) ? g_cnt[i] : 0;
            if (i < n) g_cnt[i] = 0;              // reset for next run
            int x = v;
#pragma unroll
            for (int o = 1; o < 32; o <<= 1) {
                int y = __shfl_up_sync(0xffffffffu, x, o);
                if (lane >= o) x += y;
            }
            if (lane == 31) swi[w] = x;
            __syncthreads();
            if (t < 32) {
                int s = swi[t];
#pragma unroll
                for (int o = 1; o < 32; o <<= 1) {
                    int y = __shfl_up_sync(0xffffffffu, s, o);
                    if (t >= o) s += y;
                }
                swi[t] = s;
            }
            __syncthreads();
            int pref = (w > 0) ? swi[w - 1] : 0;
            int excl = carry + pref + x - v;
            if (i < n) { g_off[i] = excl; g_cur[i] = excl; }
            carry += swi[31];
            __syncthreads();
        }
        if (t == 0) g_off[n] = carry;
        return;
    }
    int bp = blockIdx.x - withScan;
    for (int i = t; i < 4096; i += 1024) { sq[i] = Wq[i]; sk[i] = Wk[i]; sv[i] = Wv[i]; }
    __syncthreads();
    const float* h = useG ? g_h : hin;
    int lane = t & 31, w = t >> 5;
    int r0 = (bp * 32 + w) * 4;
    float h0[4], h1[4];
#pragma unroll
    for (int r = 0; r < 4; r++) {
        int row = r0 + r;
        h0[r] = (row < n) ? h[row * 64 + lane] : 0.f;
        h1[r] = (row < n) ? h[row * 64 + lane + 32] : 0.f;
    }
    float aq0[4] = {0,0,0,0}, aq1[4] = {0,0,0,0};
    float ak0[4] = {0,0,0,0}, ak1[4] = {0,0,0,0};
    float av0[4] = {0,0,0,0}, av1[4] = {0,0,0,0};
#pragma unroll
    for (int j = 0; j < 32; j++) {
        float wq0 = sq[j * 64 + lane], wq1 = sq[j * 64 + lane + 32];
        float wk0 = sk[j * 64 + lane], wk1 = sk[j * 64 + lane + 32];
        float wv0 = sv[j * 64 + lane], wv1 = sv[j * 64 + lane + 32];
#pragma unroll
        for (int r = 0; r < 4; r++) {
            float hj = __shfl_sync(0xffffffffu, h0[r], j);
            aq0[r] += hj * wq0; aq1[r] += hj * wq1;
            ak0[r] += hj * wk0; ak1[r] += hj * wk1;
            av0[r] += hj * wv0; av1[r] += hj * wv1;
        }
    }
#pragma unroll
    for (int j = 0; j < 32; j++) {
        float wq0 = sq[(j + 32) * 64 + lane], wq1 = sq[(j + 32) * 64 + lane + 32];
        float wk0 = sk[(j + 32) * 64 + lane], wk1 = sk[(j + 32) * 64 + lane + 32];
        float wv0 = sv[(j + 32) * 64 + lane], wv1 = sv[(j + 32) * 64 + lane + 32];
#pragma unroll
        for (int r = 0; r < 4; r++) {
            float hj = __shfl_sync(0xffffffffu, h1[r], j);
            aq0[r] += hj * wq0; aq1[r] += hj * wq1;
            ak0[r] += hj * wk0; ak1[r] += hj * wk1;
            av0[r] += hj * wv0; av1[r] += hj * wv1;
        }
    }
#pragma unroll
    for (int r = 0; r < 4; r++) {
        int row = r0 + r;
        if (row >= n) break;
        g_q[row * 64 + lane] = aq0[r]; g_q[row * 64 + lane + 32] = aq1[r];
        g_k[row * 64 + lane] = ak0[r]; g_k[row * 64 + lane + 32] = ak1[r];
        g_v[row * 64 + lane] = av0[r]; g_v[row * 64 + lane + 32] = av1[r];
    }
}

// ---------------- fused scatter + layer-0 bias ----------------
__global__ void k_scatbias(const int* __restrict__ src, const int* __restrict__ dstp,
                           const float* __restrict__ ef, const float* __restrict__ We, int e) {
    __shared__ float sW[128];
    __shared__ float buf[4][32 * 33];
    int t = threadIdx.x;
    if (t < 128) sW[t] = We[t];
    __syncthreads();
    int w = t >> 5, lane = t & 31;
    int base = (blockIdx.x * 4 + w) * 32;
    float* b = buf[w];
    int ed0 = base + lane;
    int slot = -1;
    if (ed0 < e) {
        int d = __ldg(dstp + ed0);
        slot = atomicAdd(&g_cur[d], 1);
        g_epk[slot] = __ldg(src + ed0);
        g_slot[ed0] = slot;
    }
#pragma unroll 4
    for (int j = 0; j < 32; j++) {
        int ed = base + j;
        b[j * 33 + lane] = (ed < e) ? __ldg(ef + (size_t)ed * 32 + lane) : 0.f;
    }
    __syncwarp();
    if (ed0 >= e) return;
    float4 bb = make_float4(0.f, 0.f, 0.f, 0.f);
#pragma unroll
    for (int k = 0; k < 32; k++) {
        float ek = b[lane * 33 + k];
        float4 wv = *(const float4*)(sW + k * 4);
        bb.x += ek * wv.x; bb.y += ek * wv.y; bb.z += ek * wv.z; bb.w += ek * wv.w;
    }
    ((float4*)g_bias)[slot] = bb;
}

// ---------------- attention: warp/node, unroll-4, hoisted loads ----------------
__global__ void k_attn(int n) {
    int lane = threadIdx.x & 31;
    int node = blockIdx.x * 8 + (threadIdx.x >> 5);
    if (node >= n) return;
    int half = lane >> 4;
    int sub = lane & 15;
    int head = sub >> 2;
    int beg = g_off[node], end = g_off[node + 1];
    if (beg >= end) {
        if (half == 0)
            *(float4*)(g_agg + (size_t)node * 64 + sub * 4) = make_float4(0.f, 0.f, 0.f, 0.f);
        return;
    }
    float4 q4 = *(const float4*)(g_q + (size_t)node * 64 + sub * 4);
    q4.x *= 0.25f; q4.y *= 0.25f; q4.z *= 0.25f; q4.w *= 0.25f;
    float4 acc = make_float4(0.f, 0.f, 0.f, 0.f);
    float d = 0.f;
    for (int p = beg; p < end; p += 4) {
        int i0 = p + half;
        int i1 = p + 2 + half;
        bool u0 = (i0 < end), u1 = (i1 < end);
        int e0 = u0 ? i0 : beg;          // clamped reads stay in-bounds
        int e1 = u1 ? i1 : beg;
        int s0 = __ldg(&g_epk[e0]);
        int s1 = __ldg(&g_epk[e1]);
        float4 k0 = __ldg((const float4*)(g_k + (size_t)s0 * 64) + sub);
        float4 k1 = __ldg((const float4*)(g_k + (size_t)s1 * 64) + sub);
        float4 w0 = __ldg((const float4*)(g_v + (size_t)s0 * 64) + sub);
        float4 w1 = __ldg((const float4*)(g_v + (size_t)s1 * 64) + sub);
        float b0 = __ldg(g_bias + (size_t)e0 * 4 + head);
        float b1 = __ldg(g_bias + (size_t)e1 * 4 + head);
        float dt0 = q4.x * k0.x + q4.y * k0.y + q4.z * k0.z + q4.w * k0.w;
        float dt1 = q4.x * k1.x + q4.y * k1.y + q4.z * k1.z + q4.w * k1.w;
        dt0 += __shfl_xor_sync(0xffffffffu, dt0, 1);
        dt1 += __shfl_xor_sync(0xffffffffu, dt1, 1);
        dt0 += __shfl_xor_sync(0xffffffffu, dt0, 2);
        dt1 += __shfl_xor_sync(0xffffffffu, dt1, 2);
        float ex0 = u0 ? __expf(dt0 + b0) : 0.f;
        float ex1 = u1 ? __expf(dt1 + b1) : 0.f;
        d += ex0; d += ex1;
        acc.x += ex0 * w0.x; acc.y += ex0 * w0.y; acc.z += ex0 * w0.z; acc.w += ex0 * w0.w;
        acc.x += ex1 * w1.x; acc.y += ex1 * w1.y; acc.z += ex1 * w1.z; acc.w += ex1 * w1.w;
    }
    acc.x += __shfl_xor_sync(0xffffffffu, acc.x, 16);
    acc.y += __shfl_xor_sync(0xffffffffu, acc.y, 16);
    acc.z += __shfl_xor_sync(0xffffffffu, acc.z, 16);
    acc.w += __shfl_xor_sync(0xffffffffu, acc.w, 16);
    d     += __shfl_xor_sync(0xffffffffu, d, 16);
    if (half == 0) {
        float inv = 1.f / (d + 1e-9f);
        float4 o;
        o.x = acc.x * inv; o.y = acc.y * inv;
        o.z = acc.z * inv; o.w = acc.w * inv;
        *(float4*)(g_agg + (size_t)node * 64 + sub * 4) = o;
    }
}

// ---------------- node update: h = LN(h + agg@Wo); fused A,B = h_new @ Wem[0:128] ----------------
__global__ void k_lnnode(const float* __restrict__ hin, int useGin,
                         const float* __restrict__ Wo, const float* __restrict__ gn,
                         const float* __restrict__ bn, const float* __restrict__ Wab,
                         float* __restrict__ outp, int useOut, int doAB, int n) {
    __shared__ float sWo[4096];
    __shared__ float sAB[4096];
    for (int i = threadIdx.x; i < 4096; i += 256) {
        sWo[i] = Wo[i];
        if (doAB) sAB[i] = Wab[i];
    }
    __syncthreads();
    int lane = threadIdx.x & 31, w = threadIdx.x >> 5;
    int row = blockIdx.x * 8 + w;
    if (row >= n) return;
    const float* h = useGin ? g_h : hin;
    float a0 = g_agg[row * 64 + lane], a1 = g_agg[row * 64 + lane + 32];
    float o0 = 0.f, o1 = 0.f;
#pragma unroll
    for (int j = 0; j < 32; j++) {
        float aj = __shfl_sync(0xffffffffu, a0, j);
        o0 += aj * sWo[j * 64 + lane];
        o1 += aj * sWo[j * 64 + lane + 32];
    }
#pragma unroll
    for (int j = 0; j < 32; j++) {
        float aj = __shfl_sync(0xffffffffu, a1, j);
        o0 += aj * sWo[(j + 32) * 64 + lane];
        o1 += aj * sWo[(j + 32) * 64 + lane + 32];
    }
    float x0 = h[row * 64 + lane] + o0;
    float x1 = h[row * 64 + lane + 32] + o1;
    float s = x0 + x1;
#pragma unroll
    for (int o = 16; o; o >>= 1) s += __shfl_xor_sync(0xffffffffu, s, o);
    float mu = s * (1.f / 64.f);
    float d0 = x0 - mu, d1 = x1 - mu;
    float vs = d0 * d0 + d1 * d1;
#pragma unroll
    for (int o = 16; o; o >>= 1) vs += __shfl_xor_sync(0xffffffffu, vs, o);
    float inv = rsqrtf(vs * (1.f / 64.f) + 1e-5f);
    float y0 = d0 * inv * __ldg(gn + lane) + __ldg(bn + lane);
    float y1 = d1 * inv * __ldg(gn + lane + 32) + __ldg(bn + lane + 32);
    float* hp = useOut ? outp : g_h;
    hp[row * 64 + lane] = y0;
    hp[row * 64 + lane + 32] = y1;
    if (doAB) {
        float A = 0.f, B = 0.f;
#pragma unroll
        for (int j = 0; j < 32; j++) {
            float yj = __shfl_sync(0xffffffffu, y0, j);
            A += yj * sAB[j * 32 + lane];
            B += yj * sAB[(j + 64) * 32 + lane];
        }
#pragma unroll
        for (int j = 0; j < 32; j++) {
            float yj = __shfl_sync(0xffffffffu, y1, j);
            A += yj * sAB[(j + 32) * 32 + lane];
            B += yj * sAB[(j + 96) * 32 + lane];
        }
        g_A[row * 32 + lane] = A;
        g_B[row * 32 + lane] = B;
    }
}

// ---------------- edge update (single pass, f32x2 GEMM) ----------------
__global__ void k_edge(const float* __restrict__ ein, int useGE,
                       const float* __restrict__ Wem2, const float* __restrict__ bem,
                       const float* __restrict__ ge, const float* __restrict__ be,
                       const float* __restrict__ WeN,
                       const int* __restrict__ src, const int* __restrict__ dstp,
                       int e, int storeE) {
    __shared__ float sW[1024];
    __shared__ float sWeN[128];
    __shared__ float sbem[32], sge[32], sbe[32];
    __shared__ float buf[4][32 * 33];
    int t = threadIdx.x;
    for (int i = t; i < 1024; i += 128) sW[i] = Wem2[i];
    if (t < 128) sWeN[t] = WeN[t];
    if (t < 32) { sbem[t] = bem[t]; sge[t] = ge[t]; sbe[t] = be[t]; }
    __syncthreads();
    int w = t >> 5, lane = t & 31;
    int base = (blockIdx.x * 4 + w) * 32;
    float* b = buf[w];
    const float* ebase = useGE ? (const float*)g_e : ein;

#pragma unroll 4
    for (int j = 0; j < 32; j++) {
        int ed = base + j;
        b[j * 33 + lane] = (ed < e) ? __ldg(ebase + (size_t)ed * 32 + lane) : 0.f;
    }
    __syncwarp();
    float er[32];
#pragma unroll
    for (int k = 0; k < 32; k++) er[k] = b[lane * 33 + k];
    __syncwarp();

    int ed0 = base + lane;
    int s_l = (ed0 < e) ? __ldg(src + ed0)  : 0;
    int d_l = (ed0 < e) ? __ldg(dstp + ed0) : 0;

#pragma unroll 4
    for (int j = 0; j < 32; j++) {
        int sj = __shfl_sync(0xffffffffu, s_l, j);
        b[j * 33 + lane] = __ldg(g_A + (size_t)sj * 32 + lane);
    }
    __syncwarp();
    float acc[32];
#pragma unroll
    for (int k = 0; k < 32; k++) acc[k] = b[lane * 33 + k] + sbem[k];
    __syncwarp();
#pragma unroll 4
    for (int j = 0; j < 32; j++) {
        int dj = __shfl_sync(0xffffffffu, d_l, j);
        b[j * 33 + lane] = __ldg(g_B + (size_t)dj * 32 + lane);
    }
    __syncwarp();
#pragma unroll
    for (int k = 0; k < 32; k++) acc[k] += b[lane * 33 + k];
    __syncwarp();

    // e @ Wem2 on packed f32x2 (FFMA2): 16 fma2 + 1 pack per k-step
    unsigned long long acc2[16];
#pragma unroll
    for (int j = 0; j < 16; j++) acc2[j] = pk2(acc[2 * j], acc[2 * j + 1]);
#pragma unroll
    for (int k = 0; k < 32; k++) {
        unsigned long long ek2 = pk2(er[k], er[k]);
        const float4* wr = (const float4*)(sW + k * 32);
#pragma unroll
        for (int j = 0; j < 8; j++) {
            float4 ww = wr[j];
            acc2[2 * j]     = fma2(ek2, pk2(ww.x, ww.y), acc2[2 * j]);
            acc2[2 * j + 1] = fma2(ek2, pk2(ww.z, ww.w), acc2[2 * j + 1]);
        }
    }
#pragma unroll
    for (int j = 0; j < 16; j++) upk2(acc2[j], acc[2 * j], acc[2 * j + 1]);

    float mu = 0.f;
#pragma unroll
    for (int j = 0; j < 32; j++) {
        float u = acc[j];
        float z = 0.7978845608028654f * (u + 0.044715f * u * u * u);
        float th = 1.f - 2.f / (__expf(2.f * z) + 1.f);
        float x = er[j] + 0.5f * u * (1.f + th);
        acc[j] = x;
        mu += x;
    }
    mu *= (1.f / 32.f);
    float var = 0.f;
#pragma unroll
    for (int j = 0; j < 32; j++) { float dx = acc[j] - mu; var += dx * dx; }
    float inv = rsqrtf(var * (1.f / 32.f) + 1e-5f);
    float4 bb = make_float4(0.f, 0.f, 0.f, 0.f);
#pragma unroll
    for (int j = 0; j < 32; j++) {
        float y = (acc[j] - mu) * inv * sge[j] + sbe[j];
        acc[j] = y;
        float4 wv = *(const float4*)(sWeN + j * 4);
        bb.x += y * wv.x; bb.y += y * wv.y; bb.z += y * wv.z; bb.w += y * wv.w;
    }
    if (ed0 < e) {
        int slot = __ldg(g_slot + ed0);
        ((float4*)g_bias)[slot] = bb;
    }
    if (storeE) {
        __syncwarp();
#pragma unroll
        for (int k = 0; k < 32; k++) b[lane * 33 + k] = acc[k];
        __syncwarp();
#pragma unroll 4
        for (int j = 0; j < 32; j++) {
            int ed = base + j;
            if (ed < e) g_e[(size_t)ed * 32 + lane] = b[j * 33 + lane];
        }
    }
}

// ---------------- launch ----------------
extern "C" void kernel_launch(void* const* d_in, const int* in_sizes, int n_in,
                              void* d_out, int out_size) {
    const float* nodef = (const float*)d_in[0];
    const float* edgef = (const float*)d_in[1];
    const int*   ei    = (const int*)d_in[2];
    const float* Wq    = (const float*)d_in[3];
    const float* Wk    = (const float*)d_in[4];
    const float* Wv    = (const float*)d_in[5];
    const float* Wo    = (const float*)d_in[6];
    const float* We    = (const float*)d_in[7];
    const float* Wem   = (const float*)d_in[8];
    const float* bem   = (const float*)d_in[9];
    const float* gn    = (const float*)d_in[10];
    const float* bn    = (const float*)d_in[11];
    const float* ge    = (const float*)d_in[12];
    const float* be    = (const float*)d_in[13];
    float* out = (float*)d_out;

    int n = in_sizes[0] / 64;
    int e = in_sizes[1] / 32;
    const int* src = ei;
    const int* dst = ei + e;
    int projBlocks = (n + 127) / 128;

    // 0: count   1: scan(+zero cnt)+proj(L0)   2: scatter+bias0   3: attn(L0) <- profiled
    k_count<<<(e + 255) / 256, 256>>>(dst, e);
    k_scanproj<<<projBlocks + 1, 1024>>>(n, nodef, 0, Wq, Wk, Wv, 1);
    k_scatbias<<<(e + 127) / 128, 128>>>(src, dst, edgef, We, e);

    for (int i = 0; i < 3; i++) {
        if (i > 0)
            k_scanproj<<<projBlocks, 1024>>>(n, nodef, 1,
                                             Wq + i * 4096, Wk + i * 4096, Wv + i * 4096, 0);
        k_attn<<<(n + 7) / 8, 256>>>(n);
        int last = (i == 2);
        k_lnnode<<<(n + 7) / 8, 256>>>(nodef, (i > 0),
                                       Wo + i * 4096, gn + i * 64, bn + i * 64,
                                       Wem + i * 5120, out, last, !last, n);
        if (!last) {
            k_edge<<<(e + 127) / 128, 128>>>(edgef, (i > 0),
                                             Wem + i * 5120 + 4096, bem + i * 32,
                                             ge + i * 32, be + i * 32,
                                             We + (i + 1) * 128,
                                             src, dst, e, (i == 0) ? 1 : 0);
        }
    }
}